// round 1
// baseline (speedup 1.0000x reference)
#include <cuda_runtime.h>
#include <cstdint>

#define SLEN 512
#define BHN 256
#define NHEADS 16
#define DH 64
#define TQ 64
#define TK 64

typedef unsigned long long u64;

// ---- packed f32x2 helpers (Blackwell sm_100+; ptxas emits FFMA2) ----
__device__ __forceinline__ u64 fma2(u64 a, u64 b, u64 c){
    u64 d; asm("fma.rn.f32x2 %0, %1, %2, %3;" : "=l"(d) : "l"(a), "l"(b), "l"(c)); return d;
}
__device__ __forceinline__ u64 mul2(u64 a, u64 b){
    u64 d; asm("mul.rn.f32x2 %0, %1, %2;" : "=l"(d) : "l"(a), "l"(b)); return d;
}
__device__ __forceinline__ u64 pack2(float lo, float hi){
    u64 d; asm("mov.b64 %0, {%1,%2};" : "=l"(d) : "f"(lo), "f"(hi)); return d;
}
__device__ __forceinline__ void unpack2(u64 v, float& lo, float& hi){
    asm("mov.b64 {%0,%1}, %2;" : "=f"(lo), "=f"(hi) : "l"(v));
}

// smem layout in u64 words (8B). Each tile row = 64 floats = 32 words,
// swizzled: word(row,dp) = row*32 ^ (dp ^ ((row>>2)&15))  -> conflict-free
// for all score-phase access patterns (rows stepping by 4 across lanes).
#define SQ_OFF   0      // Q     64x64 f32 (2048 w)
#define SKQ_OFF  2048   // K@q-rows (bias operand)
#define SK_OFF   4096   // K tile
#define SV_OFF   6144   // V tile
#define SE_OFF   8192   // E band 128x64 f32 (4096 w); aliased by Pdup 64x64 u64
#define SMEM_U64 12288  // 96 KB

__global__ void __launch_bounds__(256, 2)
attn_relbias_kernel(const float* __restrict__ q, const float* __restrict__ k,
                    const float* __restrict__ v, const float* __restrict__ emb,
                    float* __restrict__ out)
{
    extern __shared__ u64 sm[];
    const int tid = threadIdx.x;
    const int tx = tid & 15, ty = tid >> 4;
    const int bh = blockIdx.x;
    const int h  = bh & (NHEADS - 1);
    const int i0 = blockIdx.y * TQ;

    u64* Q64  = sm + SQ_OFF;
    u64* KQ64 = sm + SKQ_OFF;
    u64* K64  = sm + SK_OFF;
    u64* V64  = sm + SV_OFF;
    u64* E64  = sm + SE_OFF;   // also serves as duplicated-P buffer

    // ---- load Q tile and K@q-rows tile (kept all 8 key-tiles) ----
    for (int idx = tid; idx < 1024; idx += 256){
        int row = idx >> 4, seg = idx & 15;
        int gi = i0 + row;
        const float4 qa = *reinterpret_cast<const float4*>(q + ((size_t)gi*BHN + bh)*DH + seg*4);
        const float4 ka = *reinterpret_cast<const float4*>(k + ((size_t)gi*BHN + bh)*DH + seg*4);
        int sw = (row >> 2) & 15;
        int w0 = (row*32) ^ ((2*seg)   ^ sw);
        int w1 = (row*32) ^ ((2*seg+1) ^ sw);
        union { float2 f2; u64 u; } c;
        c.f2 = make_float2(qa.x, qa.y); Q64[w0]  = c.u;
        c.f2 = make_float2(qa.z, qa.w); Q64[w1]  = c.u;
        c.f2 = make_float2(ka.x, ka.y); KQ64[w0] = c.u;
        c.f2 = make_float2(ka.z, ka.w); KQ64[w1] = c.u;
    }

    // ---- per-thread swizzled base indices (XOR-with-dp addressing trick) ----
    int qidx[4], kidx[4], eidx[7], prow[4];
    #pragma unroll
    for (int a = 0; a < 4; a++){ int r = 4*ty + a; qidx[a] = (r*32) ^ (ty & 15); prow[a] = r*64; }
    #pragma unroll
    for (int b = 0; b < 4; b++){ int r = 4*tx + b; kidx[b] = (r*32) ^ (tx & 15); }
    {
        int ubase = 4*(tx - ty + 15);          // u0 in [0,120]
        #pragma unroll
        for (int t = 0; t < 7; t++){
            int u = ubase + t;                  // band row u = c - di + 63
            eidx[t] = (u*32) ^ ((u >> 2) & 15);
        }
    }

    u64 O2[4][2];
    #pragma unroll
    for (int a = 0; a < 4; a++){ O2[a][0] = 0ull; O2[a][1] = 0ull; }
    float mrow[4], lrow[4];
    #pragma unroll
    for (int a = 0; a < 4; a++){ mrow[a] = -1e30f; lrow[a] = 0.f; }

    const float scale = 0.125f;  // 1/sqrt(64)
    const int vb0 = 2*tx, vb1 = 2*tx + 1;

    for (int t8 = 0; t8 < SLEN/TK; ++t8){
        const int j0 = t8 * TK;
        __syncthreads();   // previous PV reads of Pdup/V done

        // ---- load K, V key-tiles ----
        for (int idx = tid; idx < 1024; idx += 256){
            int row = idx >> 4, seg = idx & 15;
            int gj = j0 + row;
            const float4 ka = *reinterpret_cast<const float4*>(k + ((size_t)gj*BHN + bh)*DH + seg*4);
            const float4 va = *reinterpret_cast<const float4*>(v + ((size_t)gj*BHN + bh)*DH + seg*4);
            int sw = (row >> 2) & 15;
            int w0 = (row*32) ^ ((2*seg)   ^ sw);
            int w1 = (row*32) ^ ((2*seg+1) ^ sw);
            union { float2 f2; u64 u; } c;
            c.f2 = make_float2(ka.x, ka.y); K64[w0] = c.u;
            c.f2 = make_float2(ka.z, ka.w); K64[w1] = c.u;
            c.f2 = make_float2(va.x, va.y); V64[w0] = c.u;
            c.f2 = make_float2(va.z, va.w); V64[w1] = c.u;
        }
        // ---- load emb band: 128 rows starting at r = j0-i0+448 ----
        {
            int rbase = j0 - i0 + 448;
            for (int idx = tid; idx < 2048; idx += 256){
                int row = idx >> 4, seg = idx & 15;
                int r = rbase + row;
                u64 e0 = 0ull, e1 = 0ull;
                if (r <= 1022){
                    const float4 ea = *reinterpret_cast<const float4*>(emb + ((size_t)h*1023 + r)*DH + seg*4);
                    union { float2 f2; u64 u; } c;
                    c.f2 = make_float2(ea.x, ea.y); e0 = c.u;
                    c.f2 = make_float2(ea.z, ea.w); e1 = c.u;
                }
                int sw = (row >> 2) & 15;
                E64[(row*32) ^ ((2*seg)   ^ sw)] = e0;
                E64[(row*32) ^ ((2*seg+1) ^ sw)] = e1;
            }
        }
        __syncthreads();

        // ---- score tile: S[i,j] = q_i.k_j + kq_i.e_{j-i+511}, packed over d ----
        u64 acc[4][4];
        #pragma unroll
        for (int a = 0; a < 4; a++)
            #pragma unroll
            for (int b = 0; b < 4; b++) acc[a][b] = 0ull;

        #pragma unroll 4
        for (int dp = 0; dp < 32; ++dp){
            u64 qv[4], kqv[4], kv[4], ev[7];
            #pragma unroll
            for (int a = 0; a < 4; a++){ qv[a] = Q64[qidx[a]^dp]; kqv[a] = KQ64[qidx[a]^dp]; }
            #pragma unroll
            for (int b = 0; b < 4; b++) kv[b] = K64[kidx[b]^dp];
            #pragma unroll
            for (int t = 0; t < 7; t++) ev[t] = E64[eidx[t]^dp];
            #pragma unroll
            for (int a = 0; a < 4; a++)
                #pragma unroll
                for (int b = 0; b < 4; b++){
                    acc[a][b] = fma2(qv[a],  kv[b],       acc[a][b]);
                    acc[a][b] = fma2(kqv[a], ev[b-a+3],   acc[a][b]);
                }
        }

        // ---- online softmax (row split across the 16 tx lanes of a half-warp) ----
        float p[4][4];
        #pragma unroll
        for (int a = 0; a < 4; a++){
            float s[4];
            #pragma unroll
            for (int b = 0; b < 4; b++){
                float lo, hi; unpack2(acc[a][b], lo, hi);
                s[b] = (lo + hi) * scale;
            }
            float rm = fmaxf(fmaxf(s[0], s[1]), fmaxf(s[2], s[3]));
            #pragma unroll
            for (int msk = 1; msk < 16; msk <<= 1)
                rm = fmaxf(rm, __shfl_xor_sync(0xffffffffu, rm, msk));
            float mn   = fmaxf(mrow[a], rm);
            float corr = __expf(mrow[a] - mn);
            mrow[a] = mn;
            float rs = 0.f;
            #pragma unroll
            for (int b = 0; b < 4; b++){ p[a][b] = __expf(s[b] - mn); rs += p[a][b]; }
            #pragma unroll
            for (int msk = 1; msk < 16; msk <<= 1)
                rs += __shfl_xor_sync(0xffffffffu, rs, msk);
            lrow[a] = lrow[a]*corr + rs;
            u64 c2 = pack2(corr, corr);
            O2[a][0] = mul2(O2[a][0], c2);
            O2[a][1] = mul2(O2[a][1], c2);
        }

        __syncthreads();   // all E-band reads done; safe to overwrite with Pdup
        #pragma unroll
        for (int a = 0; a < 4; a++)
            #pragma unroll
            for (int b = 0; b < 4; b++)
                E64[prow[a] + 4*tx + b] = pack2(p[a][b], p[a][b]);  // duplicated pair
        __syncthreads();

        // ---- PV: O[i, 4tx..4tx+3] += sum_j P[i,j] * V[j,:], packed over out-cols ----
        #pragma unroll 8
        for (int j = 0; j < TK; j++){
            int vbase = (j*32) ^ ((j >> 2) & 15);
            u64 vv0 = V64[vbase ^ vb0];
            u64 vv1 = V64[vbase ^ vb1];
            #pragma unroll
            for (int a = 0; a < 4; a++){
                u64 pj = E64[prow[a] + j];
                O2[a][0] = fma2(pj, vv0, O2[a][0]);
                O2[a][1] = fma2(pj, vv1, O2[a][1]);
            }
        }
    }

    // ---- epilogue: out[i, bh, :] = O / l ----
    #pragma unroll
    for (int a = 0; a < 4; a++){
        float inv = 1.f / lrow[a];
        float x0, x1, x2, x3;
        unpack2(O2[a][0], x0, x1);
        unpack2(O2[a][1], x2, x3);
        float4 r = make_float4(x0*inv, x1*inv, x2*inv, x3*inv);
        int gi = i0 + 4*ty + a;
        *reinterpret_cast<float4*>(out + ((size_t)gi*BHN + bh)*DH + 4*tx) = r;
    }
}

extern "C" void kernel_launch(void* const* d_in, const int* in_sizes, int n_in,
                              void* d_out, int out_size)
{
    const float* q   = (const float*)d_in[0];
    const float* k   = (const float*)d_in[1];
    const float* v   = (const float*)d_in[2];
    const float* emb = (const float*)d_in[3];
    float* out = (float*)d_out;

    cudaFuncSetAttribute(attn_relbias_kernel,
                         cudaFuncAttributeMaxDynamicSharedMemorySize, SMEM_U64 * 8);

    dim3 grid(BHN, SLEN / TQ);   // (256 bh, 8 q-tiles)
    attn_relbias_kernel<<<grid, 256, SMEM_U64 * 8>>>(q, k, v, emb, out);
}

// round 7
// speedup vs baseline: 1.2558x; 1.2558x over previous
#include <cuda_runtime.h>
#include <cstdint>

#define SLEN 512
#define BHN 256
#define NHEADS 16
#define DH 64
#define TQ 128
#define TK 128

typedef unsigned long long u64;

// ---- packed f32x2 helpers (Blackwell; ptxas emits FFMA2) ----
__device__ __forceinline__ u64 fma2(u64 a, u64 b, u64 c){
    u64 d; asm("fma.rn.f32x2 %0, %1, %2, %3;" : "=l"(d) : "l"(a), "l"(b), "l"(c)); return d;
}
__device__ __forceinline__ u64 mul2(u64 a, u64 b){
    u64 d; asm("mul.rn.f32x2 %0, %1, %2;" : "=l"(d) : "l"(a), "l"(b)); return d;
}
__device__ __forceinline__ u64 pack2(float lo, float hi){
    u64 d; asm("mov.b64 %0, {%1,%2};" : "=l"(d) : "f"(lo), "f"(hi)); return d;
}
__device__ __forceinline__ void unpack2(u64 v, float& lo, float& hi){
    asm("mov.b64 {%0,%1}, %2;" : "=f"(lo), "=f"(hi) : "l"(v));
}

// Swizzle: conflict-free for rows stepping by 8 across the 16 lanes of a
// half-warp, and distinct over 16 consecutive rows (loader stores).
__device__ __forceinline__ int swz(int row){ return ((row>>3)&15) ^ ((row&7)<<1); }

// u64-word offsets in dynamic smem
#define SQ_OFF   0        // Q  128x64 f32, unswizzled (reads are broadcasts)
#define SKQ_OFF  4096     // K@q-rows, unswizzled
#define SK_OFF   8192     // K tile, swizzled
#define SV_OFF   12288    // V tile, swizzled
#define SE_OFF   16384    // E band 256x64 f32, swizzled; aliased by P (128x64 u64)
#define SMEM_U64 24576    // 192 KB

__global__ void __launch_bounds__(256, 1)
attn_relbias_kernel(const float* __restrict__ q, const float* __restrict__ k,
                    const float* __restrict__ v, const float* __restrict__ emb,
                    float* __restrict__ out)
{
    extern __shared__ u64 sm[];
    const int tid = threadIdx.x;
    const int tx = tid & 15, ty = tid >> 4;   // 16 col-groups x 16 row-groups
    const int bh = blockIdx.x;
    const int h  = bh & (NHEADS - 1);
    const int i0 = blockIdx.y * TQ;

    u64* Q64  = sm + SQ_OFF;
    u64* KQ64 = sm + SKQ_OFF;
    u64* K64  = sm + SK_OFF;
    u64* V64  = sm + SV_OFF;
    u64* E64  = sm + SE_OFF;
    u64* P64  = sm + SE_OFF;   // alias: E consumed before P written

    // ---- load Q tile + K@q-rows tile once (unswizzled) ----
    for (int idx = tid; idx < 2048; idx += 256){
        int row = idx >> 4, seg = idx & 15;
        int gi = i0 + row;
        const float4 qa = *reinterpret_cast<const float4*>(q + ((size_t)gi*BHN + bh)*DH + seg*4);
        const float4 ka = *reinterpret_cast<const float4*>(k + ((size_t)gi*BHN + bh)*DH + seg*4);
        *reinterpret_cast<float4*>(Q64  + row*32 + 2*seg) = qa;
        *reinterpret_cast<float4*>(KQ64 + row*32 + 2*seg) = ka;
    }

    // ---- compact swizzled-address bases (single LOP3 per load in hot loop) ----
    // K rows r=8tx+b: word = r*32 ^ swz(r) = 257*tx ^ 34*b  (disjoint bit fields)
    const int Kbase = 257 * tx;
    // E rows u = ub+t, ub = 8*(tx-ty)+120: split t<8 / t>=8 so 34*t' stays below bit 8
    const int ub  = 8*(tx - ty) + 120;
    const int Eb0 = (ub*32)      ^ (((ub>>3))     & 15);
    const int Eb1 = ((ub+8)*32)  ^ ((((ub+8)>>3)) & 15);
    const u64* Qb  = Q64  + ty*256;   // + a*32 + dp (immediate-folded)
    const u64* KQb = KQ64 + ty*256;

    u64 O2[8][2]; float mrow[8], lrow[8];
    #pragma unroll
    for (int a = 0; a < 8; a++){ O2[a][0]=0ull; O2[a][1]=0ull; mrow[a]=-1e30f; lrow[a]=0.f; }

    const float scale = 0.125f;     // 1/sqrt(64)
    const int vb0 = 2*tx, vb1 = 2*tx + 1;

    for (int t4 = 0; t4 < SLEN/TK; ++t4){
        const int j0 = t4 * TK;
        __syncthreads();   // previous PV done reading P(E-alias)/V

        // ---- load K, V tiles (swizzled via float4 with conditional half-swap) ----
        for (int idx = tid; idx < 2048; idx += 256){
            int row = idx >> 4, seg = idx & 15;
            int gj = j0 + row;
            float4 ka = *reinterpret_cast<const float4*>(k + ((size_t)gj*BHN + bh)*DH + seg*4);
            float4 va = *reinterpret_cast<const float4*>(v + ((size_t)gj*BHN + bh)*DH + seg*4);
            int s  = swz(row);
            int wb = (2*seg) ^ (s & ~1);
            if (s & 1){ ka = make_float4(ka.z, ka.w, ka.x, ka.y);
                        va = make_float4(va.z, va.w, va.x, va.y); }
            *reinterpret_cast<float4*>(K64 + row*32 + wb) = ka;
            *reinterpret_cast<float4*>(V64 + row*32 + wb) = va;
        }
        // ---- load E band: 255 rows at r = j0-i0+384+u  (always in [0,1022]) ----
        {
            int rb = j0 - i0 + 384;
            for (int idx = tid; idx < 255*16; idx += 256){
                int row = idx >> 4, seg = idx & 15;
                float4 ea = *reinterpret_cast<const float4*>(
                    emb + ((size_t)h*1023 + rb + row)*DH + seg*4);
                int s  = swz(row);
                int wb = (2*seg) ^ (s & ~1);
                if (s & 1) ea = make_float4(ea.z, ea.w, ea.x, ea.y);
                *reinterpret_cast<float4*>(E64 + row*32 + wb) = ea;
            }
        }
        __syncthreads();

        // ---- scores: 8x8 microtile, packed over d.  Two passes share acc. ----
        u64 acc[8][8];
        #pragma unroll
        for (int a = 0; a < 8; a++)
            #pragma unroll
            for (int b = 0; b < 8; b++) acc[a][b] = 0ull;

        // pass 1: Q.K
        #pragma unroll 2
        for (int dp = 0; dp < 32; ++dp){
            u64 kv[8];
            #pragma unroll
            for (int b = 0; b < 8; b++) kv[b] = K64[Kbase ^ (34*b) ^ dp];
            #pragma unroll
            for (int a = 0; a < 8; a++){
                u64 qa = Qb[a*32 + dp];
                #pragma unroll
                for (int b = 0; b < 8; b++) acc[a][b] = fma2(qa, kv[b], acc[a][b]);
            }
        }
        // pass 2: bias = KQ . E(diag band), t = b-a+7 in [0,14]
        #pragma unroll 2
        for (int dp = 0; dp < 32; ++dp){
            u64 ev[15];
            #pragma unroll
            for (int t = 0; t < 8; t++)  ev[t]   = E64[Eb0 ^ (34*t)     ^ dp];
            #pragma unroll
            for (int t = 0; t < 7; t++)  ev[t+8] = E64[Eb1 ^ (34*t)     ^ dp];
            #pragma unroll
            for (int a = 0; a < 8; a++){
                u64 kqa = KQb[a*32 + dp];
                #pragma unroll
                for (int b = 0; b < 8; b++) acc[a][b] = fma2(kqa, ev[b-a+7], acc[a][b]);
            }
        }

        // ---- online softmax (each row spans the 16 tx lanes of a half-warp) ----
        u64 pp[8][4];   // packed (p_j, p_{j+1}) pairs
        #pragma unroll
        for (int a = 0; a < 8; a++){
            float s[8];
            #pragma unroll
            for (int b = 0; b < 8; b++){
                float lo, hi; unpack2(acc[a][b], lo, hi);
                s[b] = (lo + hi) * scale;
            }
            float rm = s[0];
            #pragma unroll
            for (int b = 1; b < 8; b++) rm = fmaxf(rm, s[b]);
            #pragma unroll
            for (int msk = 1; msk < 16; msk <<= 1)
                rm = fmaxf(rm, __shfl_xor_sync(0xffffffffu, rm, msk));
            float mn   = fmaxf(mrow[a], rm);
            float corr = __expf(mrow[a] - mn);
            mrow[a] = mn;
            float e[8], rs = 0.f;
            #pragma unroll
            for (int b = 0; b < 8; b++){ e[b] = __expf(s[b] - mn); rs += e[b]; }
            #pragma unroll
            for (int msk = 1; msk < 16; msk <<= 1)
                rs += __shfl_xor_sync(0xffffffffu, rs, msk);
            lrow[a] = lrow[a]*corr + rs;
            u64 c2 = pack2(corr, corr);
            O2[a][0] = mul2(O2[a][0], c2);
            O2[a][1] = mul2(O2[a][1], c2);
            #pragma unroll
            for (int c = 0; c < 4; c++) pp[a][c] = pack2(e[2*c], e[2*c+1]);
        }

        __syncthreads();   // all E reads done; safe to overwrite with P
        // P store, conflict-free interleave: word(i, jp) = i*64 + (jp&3)*16 + (jp>>2)
        #pragma unroll
        for (int a = 0; a < 8; a++)
            #pragma unroll
            for (int c = 0; c < 4; c++)
                P64[(8*ty + a)*64 + c*16 + tx] = pp[a][c];
        __syncthreads();

        // ---- PV: O[i, 4tx..4tx+3] += sum_j P[i,j] V[j,:] ----
        #pragma unroll 1
        for (int qd = 0; qd < 16; ++qd){
            #pragma unroll
            for (int cc = 0; cc < 4; ++cc){
                int j   = 8*qd + 2*cc;
                int vwa = (j*32)     ^ swz(j);
                int vwb = ((j+1)*32) ^ swz(j+1);
                u64 v0a = V64[vwa ^ vb0], v0b = V64[vwa ^ vb1];
                u64 v1a = V64[vwb ^ vb0], v1b = V64[vwb ^ vb1];
                #pragma unroll
                for (int a = 0; a < 8; a++){
                    u64 pw = P64[(8*ty + a)*64 + cc*16 + qd];   // broadcast read
                    float plo, phi; unpack2(pw, plo, phi);
                    u64 d0 = pack2(plo, plo), d1 = pack2(phi, phi);
                    O2[a][0] = fma2(d0, v0a, O2[a][0]);
                    O2[a][1] = fma2(d0, v0b, O2[a][1]);
                    O2[a][0] = fma2(d1, v1a, O2[a][0]);
                    O2[a][1] = fma2(d1, v1b, O2[a][1]);
                }
            }
        }
    }

    // ---- epilogue: out[i, bh, :] = O / l ----
    #pragma unroll
    for (int a = 0; a < 8; a++){
        float inv = 1.f / lrow[a];
        float x0, x1, x2, x3;
        unpack2(O2[a][0], x0, x1);
        unpack2(O2[a][1], x2, x3);
        float4 r = make_float4(x0*inv, x1*inv, x2*inv, x3*inv);
        int gi = i0 + 8*ty + a;
        *reinterpret_cast<float4*>(out + ((size_t)gi*BHN + bh)*DH + 4*tx) = r;
    }
}

extern "C" void kernel_launch(void* const* d_in, const int* in_sizes, int n_in,
                              void* d_out, int out_size)
{
    const float* q   = (const float*)d_in[0];
    const float* k   = (const float*)d_in[1];
    const float* v   = (const float*)d_in[2];
    const float* emb = (const float*)d_in[3];
    float* out = (float*)d_out;

    cudaFuncSetAttribute(attn_relbias_kernel,
                         cudaFuncAttributeMaxDynamicSharedMemorySize, SMEM_U64 * 8);

    dim3 grid(BHN, SLEN / TQ);   // (256 bh, 4 q-tiles)
    attn_relbias_kernel<<<grid, 256, SMEM_U64 * 8>>>(q, k, v, emb, out);
}

// round 13
// speedup vs baseline: 1.7378x; 1.3838x over previous
#include <cuda_runtime.h>
#include <cuda_bf16.h>
#include <cstdint>

typedef uint32_t u32;
typedef uint64_t u64;

#define BHN 256
#define NHEADS 16
#define DH 64
#define TQ 128
#define TK 128

// ---- smem byte offsets ----
#define SM_QH 0        // Q hi    128x64 bf16 (16 KB), persists
#define SM_QL 16384    // Q lo
#define SM_GH 32768    // K@q-rows hi (bias A operand), persists
#define SM_GL 49152
#define SM_KH 65536    // K tile hi; later aliased by V^T hi (64 rows x 128 j)
#define SM_KL 81920
#define SM_EH 98304    // E band half: 128 rows x 64 bf16 (16 KB)
#define SM_EL 114688
#define SM_SC 131072   // score f32 128x128 (64 KB); later Ph(32K)+Pl(32K)
#define SM_PH 131072
#define SM_PL 163840
#define SM_CR 196608   // corr[128] f32
#define SM_LI 197120   // linv[128] f32
#define SM_TOTAL 197632

__device__ __forceinline__ void MMA(float* c, u32 a0, u32 a1, u32 a2, u32 a3, u32 b0, u32 b1){
    asm volatile("mma.sync.aligned.m16n8k16.row.col.f32.bf16.bf16.f32 "
        "{%0,%1,%2,%3}, {%4,%5,%6,%7}, {%8,%9}, {%0,%1,%2,%3};"
        : "+f"(c[0]), "+f"(c[1]), "+f"(c[2]), "+f"(c[3])
        : "r"(a0), "r"(a1), "r"(a2), "r"(a3), "r"(b0), "r"(b1));
}

// fragment word loads; rows of 32 words (64 bf16) or 64 words (128 bf16)
__device__ __forceinline__ u32 ldf32w(const u32* buf, int row, int kw, int lane4){
    return buf[row*32 + ((kw + lane4) ^ ((row & 7) << 2))];
}
__device__ __forceinline__ u32 ldf64w(const u32* buf, int row, int kw, int lane4){
    return buf[row*64 + ((kw + lane4) ^ ((row & 7) << 2))];
}
// score swizzle: float word index for (r, c)
__device__ __forceinline__ int sidx(int r, int c){
    return r*128 + 2*((c >> 1) ^ ((r & 7) << 2)) + (c & 1);
}

__device__ __forceinline__ void split2(float x0, float x1, u32 &H, u32 &L){
    __nv_bfloat162 hv = __floats2bfloat162_rn(x0, x1);
    __nv_bfloat162 lv = __floats2bfloat162_rn(x0 - __bfloat162float(hv.x),
                                              x1 - __bfloat162float(hv.y));
    H = *reinterpret_cast<u32*>(&hv);
    L = *reinterpret_cast<u32*>(&lv);
}
__device__ __forceinline__ void splitpack4(float4 a, u64 &H, u64 &L){
    u32 h0,l0,h1,l1;
    split2(a.x, a.y, h0, l0);
    split2(a.z, a.w, h1, l1);
    H = (u64)h0 | ((u64)h1 << 32);
    L = (u64)l0 | ((u64)l1 << 32);
}
// store one hi/lo u64 pair into a 32-word-row bf16 tile with the frag swizzle
__device__ __forceinline__ void st_hl(u32* bufH, u32* bufL, int row, int sg, u64 Hv, u64 Lv){
    int w = row*32 + ((2*sg) ^ ((row & 7) << 2));
    *reinterpret_cast<u64*>(bufH + w) = Hv;
    *reinterpret_cast<u64*>(bufL + w) = Lv;
}

__global__ void __launch_bounds__(256, 1)
attn_mma_kernel(const float* __restrict__ q, const float* __restrict__ k,
                const float* __restrict__ v, const float* __restrict__ emb,
                float* __restrict__ out)
{
    extern __shared__ char smc[];
    u32* QH = (u32*)(smc + SM_QH);  u32* QL = (u32*)(smc + SM_QL);
    u32* GH = (u32*)(smc + SM_GH);  u32* GL = (u32*)(smc + SM_GL);
    u32* KH = (u32*)(smc + SM_KH);  u32* KL = (u32*)(smc + SM_KL);   // also V^T
    u32* EH = (u32*)(smc + SM_EH);  u32* EL = (u32*)(smc + SM_EL);
    u32* PH = (u32*)(smc + SM_PH);  u32* PL = (u32*)(smc + SM_PL);
    float* SC = (float*)(smc + SM_SC);
    float* CR = (float*)(smc + SM_CR);
    float* LI = (float*)(smc + SM_LI);

    const int tid = threadIdx.x;
    const int T = tid & 31, W = tid >> 5;
    const int lane4 = T & 3, g4 = T >> 2;
    const int wm  = (W >> 1) * 32;   // warp row base (QK/band/PV share)
    const int wn  = (W & 1) * 64;    // warp col base for 128-wide C
    const int wnp = (W & 1) * 32;    // warp col base for PV (64-wide C)
    const int bh = blockIdx.x, h = bh & (NHEADS - 1);
    const int i0 = blockIdx.y * TQ;
    const float scale = 0.125f;

    // ---- prologue: load+split Q and K@q-rows ----
    for (int it = 0; it < 8; it++){
        int idx = tid + 256*it;
        int row = idx >> 4, sg = idx & 15;
        size_t g = ((size_t)(i0 + row) * BHN + bh) * DH + sg * 4;
        float4 qa = *(const float4*)(q + g);
        float4 ka = *(const float4*)(k + g);
        u64 H, L;
        splitpack4(qa, H, L); st_hl(QH, QL, row, sg, H, L);
        splitpack4(ka, H, L); st_hl(GH, GL, row, sg, H, L);
    }

    float O[2][4][4];
    #pragma unroll
    for (int a = 0; a < 2; a++)
        #pragma unroll
        for (int b = 0; b < 4; b++)
            #pragma unroll
            for (int c = 0; c < 4; c++) O[a][b][c] = 0.f;
    float mrun = -1e30f, lrun = 0.f;

    #pragma unroll 1
    for (int t = 0; t < 4; t++){
        const int j0 = t * TK;
        __syncthreads();   // prev tile's PV mma done reading V^T (aliased with K)

        // ---- load K tile + E half0 ----
        for (int it = 0; it < 8; it++){
            int idx = tid + 256*it;
            int row = idx >> 4, sg = idx & 15;
            size_t g = ((size_t)(j0 + row) * BHN + bh) * DH + sg * 4;
            float4 ka = *(const float4*)(k + g);
            u64 H, L; splitpack4(ka, H, L);
            st_hl(KH, KL, row, sg, H, L);
        }
        {
            int rb = j0 - i0 + 384;   // E half0 global base
            for (int it = 0; it < 8; it++){
                int idx = tid + 256*it;
                int row = idx >> 4, sg = idx & 15;
                int gr = rb + row;
                u64 H = 0ull, L = 0ull;
                if (gr <= 1022){
                    float4 ea = *(const float4*)(emb + ((size_t)h*1023 + gr)*DH + sg*4);
                    splitpack4(ea, H, L);
                }
                st_hl(EH, EL, row, sg, H, L);
            }
        }
        __syncthreads();

        // ---- QK^T: 3 hi/lo splits ----
        {
            float C[2][8][4];
            #pragma unroll
            for (int a = 0; a < 2; a++)
                #pragma unroll
                for (int b = 0; b < 8; b++)
                    #pragma unroll
                    for (int c = 0; c < 4; c++) C[a][b][c] = 0.f;
            #pragma unroll
            for (int s = 0; s < 3; s++){
                const u32* Ab = (s == 2) ? QL : QH;
                const u32* Bb = (s == 1) ? KL : KH;
                #pragma unroll
                for (int ks = 0; ks < 4; ks++){
                    int kw = ks * 8;
                    u32 a[2][4];
                    #pragma unroll
                    for (int mf = 0; mf < 2; mf++){
                        int rb = wm + mf*16;
                        a[mf][0] = ldf32w(Ab, rb + g4,     kw,     lane4);
                        a[mf][1] = ldf32w(Ab, rb + 8 + g4, kw,     lane4);
                        a[mf][2] = ldf32w(Ab, rb + g4,     kw + 4, lane4);
                        a[mf][3] = ldf32w(Ab, rb + 8 + g4, kw + 4, lane4);
                    }
                    #pragma unroll
                    for (int nf = 0; nf < 8; nf++){
                        int nb = wn + nf*8;
                        u32 b0 = ldf32w(Bb, nb + g4, kw,     lane4);
                        u32 b1 = ldf32w(Bb, nb + g4, kw + 4, lane4);
                        MMA(C[0][nf], a[0][0], a[0][1], a[0][2], a[0][3], b0, b1);
                        MMA(C[1][nf], a[1][0], a[1][1], a[1][2], a[1][3], b0, b1);
                    }
                }
            }
            // store to score smem
            #pragma unroll
            for (int mf = 0; mf < 2; mf++)
                #pragma unroll
                for (int nf = 0; nf < 8; nf++){
                    int r = wm + mf*16 + g4;
                    int c = wn + nf*8 + lane4*2;
                    *reinterpret_cast<float2*>(SC + sidx(r, c))     = make_float2(C[mf][nf][0], C[mf][nf][1]);
                    *reinterpret_cast<float2*>(SC + sidx(r + 8, c)) = make_float2(C[mf][nf][2], C[mf][nf][3]);
                }
        }
        __syncthreads();   // score tile complete

        // ---- band halves: D'[i,u] = KQ . E, shear-add into score ----
        #pragma unroll 1
        for (int hh = 0; hh < 2; hh++){
            if (hh == 1){
                __syncthreads();   // half0 E reads done
                int rb = j0 - i0 + 384 + 128;
                for (int it = 0; it < 8; it++){
                    int idx = tid + 256*it;
                    int row = idx >> 4, sg = idx & 15;
                    int gr = rb + row;
                    u64 H = 0ull, L = 0ull;
                    if (gr <= 1022){
                        float4 ea = *(const float4*)(emb + ((size_t)h*1023 + gr)*DH + sg*4);
                        splitpack4(ea, H, L);
                    }
                    st_hl(EH, EL, row, sg, H, L);
                }
                // V^T build (K tile free now): Vt[d][jpair] hi/lo
                for (int it = 0; it < 4; it++){
                    int idx = tid + 256*it;
                    int jp = idx & 63, ds = idx >> 6;
                    union { float4 v4; float f[4]; } A2, B2;
                    A2.v4 = *(const float4*)(v + ((size_t)(j0 + 2*jp    ) * BHN + bh) * DH + 4*ds);
                    B2.v4 = *(const float4*)(v + ((size_t)(j0 + 2*jp + 1) * BHN + bh) * DH + 4*ds);
                    #pragma unroll
                    for (int e = 0; e < 4; e++){
                        int d = 4*ds + e;
                        u32 hi, lo; split2(A2.f[e], B2.f[e], hi, lo);
                        int wv = d*64 + (jp ^ ((d & 7) << 2));
                        KH[wv] = hi; KL[wv] = lo;
                    }
                }
                __syncthreads();
            }
            float C[2][8][4];
            #pragma unroll
            for (int a = 0; a < 2; a++)
                #pragma unroll
                for (int b = 0; b < 8; b++)
                    #pragma unroll
                    for (int c = 0; c < 4; c++) C[a][b][c] = 0.f;
            #pragma unroll
            for (int s = 0; s < 3; s++){
                const u32* Ab = (s == 2) ? GL : GH;
                const u32* Bb = (s == 1) ? EL : EH;
                #pragma unroll
                for (int ks = 0; ks < 4; ks++){
                    int kw = ks * 8;
                    u32 a[2][4];
                    #pragma unroll
                    for (int mf = 0; mf < 2; mf++){
                        int rb = wm + mf*16;
                        a[mf][0] = ldf32w(Ab, rb + g4,     kw,     lane4);
                        a[mf][1] = ldf32w(Ab, rb + 8 + g4, kw,     lane4);
                        a[mf][2] = ldf32w(Ab, rb + g4,     kw + 4, lane4);
                        a[mf][3] = ldf32w(Ab, rb + 8 + g4, kw + 4, lane4);
                    }
                    #pragma unroll
                    for (int nf = 0; nf < 8; nf++){
                        int nb = wn + nf*8;
                        u32 b0 = ldf32w(Bb, nb + g4, kw,     lane4);
                        u32 b1 = ldf32w(Bb, nb + g4, kw + 4, lane4);
                        MMA(C[0][nf], a[0][0], a[0][1], a[0][2], a[0][3], b0, b1);
                        MMA(C[1][nf], a[1][0], a[1][1], a[1][2], a[1][3], b0, b1);
                    }
                }
            }
            // shear-add: score[r][u + r - 127] += C  (bijective -> no races)
            #pragma unroll
            for (int mf = 0; mf < 2; mf++)
                #pragma unroll
                for (int nf = 0; nf < 8; nf++){
                    int r0 = wm + mf*16 + g4, r1 = r0 + 8;
                    int u  = hh*128 + wn + nf*8 + lane4*2;
                    int ja = u + r0 - 127;
                    int jb = u + r1 - 127;
                    if ((unsigned)ja     < 128u) SC[sidx(r0, ja)]     += C[mf][nf][0];
                    if ((unsigned)(ja+1) < 128u) SC[sidx(r0, ja + 1)] += C[mf][nf][1];
                    if ((unsigned)jb     < 128u) SC[sidx(r1, jb)]     += C[mf][nf][2];
                    if ((unsigned)(jb+1) < 128u) SC[sidx(r1, jb + 1)] += C[mf][nf][3];
                }
        }
        __syncthreads();   // final scores in smem

        // ---- softmax: thread pair per row (r = tid>>1, col half = tid&1) ----
        {
            int r = tid >> 1, hf = tid & 1, cb = hf * 64;
            float sv[64];
            #pragma unroll
            for (int p = 0; p < 32; p++){
                float2 t2 = *reinterpret_cast<float2*>(
                    SC + r*128 + 2*(((cb >> 1) + p) ^ ((r & 7) << 2)));
                sv[2*p] = t2.x; sv[2*p+1] = t2.y;
            }
            float rm = sv[0];
            #pragma unroll
            for (int e = 1; e < 64; e++) rm = fmaxf(rm, sv[e]);
            rm = fmaxf(rm, __shfl_xor_sync(0xffffffffu, rm, 1));
            float mn = fmaxf(mrun, rm * scale);
            float corr = __expf(mrun - mn);
            mrun = mn;
            float rs = 0.f;
            #pragma unroll
            for (int e = 0; e < 64; e++){ sv[e] = __expf(sv[e]*scale - mn); rs += sv[e]; }
            rs += __shfl_xor_sync(0xffffffffu, rs, 1);
            lrun = lrun * corr + rs;
            if (hf == 0) CR[r] = corr;
            __syncthreads();   // all score reads done; safe to overwrite with P
            #pragma unroll
            for (int p = 0; p < 32; p++){
                u32 hi, lo; split2(sv[2*p], sv[2*p+1], hi, lo);
                int wv = r*64 + ((((cb >> 1) + p)) ^ ((r & 7) << 2));
                PH[wv] = hi; PL[wv] = lo;
            }
        }
        __syncthreads();

        // ---- PV: O = O*corr + P . V ----
        {
            float cr0[2], cr1[2];
            #pragma unroll
            for (int mf = 0; mf < 2; mf++){
                cr0[mf] = CR[wm + mf*16 + g4];
                cr1[mf] = CR[wm + mf*16 + 8 + g4];
            }
            #pragma unroll
            for (int mf = 0; mf < 2; mf++)
                #pragma unroll
                for (int nf = 0; nf < 4; nf++){
                    O[mf][nf][0] *= cr0[mf]; O[mf][nf][1] *= cr0[mf];
                    O[mf][nf][2] *= cr1[mf]; O[mf][nf][3] *= cr1[mf];
                }
            #pragma unroll
            for (int s = 0; s < 3; s++){
                const u32* Ab = (s == 2) ? PL : PH;
                const u32* Bb = (s == 1) ? KL : KH;   // V^T lo / hi
                #pragma unroll
                for (int ks = 0; ks < 8; ks++){
                    int kw = ks * 8;
                    u32 a[2][4];
                    #pragma unroll
                    for (int mf = 0; mf < 2; mf++){
                        int rb = wm + mf*16;
                        a[mf][0] = ldf64w(Ab, rb + g4,     kw,     lane4);
                        a[mf][1] = ldf64w(Ab, rb + 8 + g4, kw,     lane4);
                        a[mf][2] = ldf64w(Ab, rb + g4,     kw + 4, lane4);
                        a[mf][3] = ldf64w(Ab, rb + 8 + g4, kw + 4, lane4);
                    }
                    #pragma unroll
                    for (int nf = 0; nf < 4; nf++){
                        int nb = wnp + nf*8;
                        u32 b0 = ldf64w(Bb, nb + g4, kw,     lane4);
                        u32 b1 = ldf64w(Bb, nb + g4, kw + 4, lane4);
                        MMA(O[0][nf], a[0][0], a[0][1], a[0][2], a[0][3], b0, b1);
                        MMA(O[1][nf], a[1][0], a[1][1], a[1][2], a[1][3], b0, b1);
                    }
                }
            }
        }
    }

    // ---- epilogue ----
    if ((tid & 1) == 0) LI[tid >> 1] = 1.f / lrun;
    __syncthreads();
    #pragma unroll
    for (int mf = 0; mf < 2; mf++){
        int r0 = wm + mf*16 + g4, r1 = r0 + 8;
        float li0 = LI[r0], li1 = LI[r1];
        #pragma unroll
        for (int nf = 0; nf < 4; nf++){
            int c = wnp + nf*8 + lane4*2;
            *reinterpret_cast<float2*>(out + ((size_t)(i0 + r0) * BHN + bh) * DH + c)
                = make_float2(O[mf][nf][0] * li0, O[mf][nf][1] * li0);
            *reinterpret_cast<float2*>(out + ((size_t)(i0 + r1) * BHN + bh) * DH + c)
                = make_float2(O[mf][nf][2] * li1, O[mf][nf][3] * li1);
        }
    }
}

extern "C" void kernel_launch(void* const* d_in, const int* in_sizes, int n_in,
                              void* d_out, int out_size)
{
    const float* q   = (const float*)d_in[0];
    const float* k   = (const float*)d_in[1];
    const float* v   = (const float*)d_in[2];
    const float* emb = (const float*)d_in[3];
    float* out = (float*)d_out;

    cudaFuncSetAttribute(attn_mma_kernel,
                         cudaFuncAttributeMaxDynamicSharedMemorySize, SM_TOTAL);
    dim3 grid(BHN, 512 / TQ);   // (256 bh, 4 q-tiles)
    attn_mma_kernel<<<grid, 256, SM_TOTAL>>>(q, k, v, emb, out);
}